// round 14
// baseline (speedup 1.0000x reference)
#include <cuda_runtime.h>
#include <cstdint>

// predict/target: [2, 4, 64, 256, 256] fp32 -> 512 slices of 65536 elems.
#define HW              65536
#define NSLICES         512
#define SLICE_D         64
#define NPAIRS          8
#define TPB             256
#define CTAS_PER_SLICE  8
#define GRID            (NSLICES * CTAS_PER_SLICE)       // 4096
#define CHUNK_F4        (HW / 4 / CTAS_PER_SLICE)        // 2048 float4 per CTA/tensor
#define STAGE_F4        512                              // 8KB per tensor per stage
#define NSTAGES         (CHUNK_F4 / STAGE_F4)            // 4
#define KBUF            3                                // triple buffer, 48 KB ring
#define F4_PER_THREAD   (STAGE_F4 / TPB)                 // 2

__device__ float        g_num[NSLICES];
__device__ float        g_sp [NSLICES];
__device__ float        g_st [NSLICES];
__device__ float        g_valid[NSLICES];
__device__ unsigned int g_done;

// sigmoid(x) = 0.5 * tanh(0.5 x) + 0.5  (tanh.approx.f32: 1 MUFU op)
__device__ __forceinline__ float fast_sigmoid(float x) {
    float t;
    asm("tanh.approx.f32 %0, %1;" : "=f"(t) : "f"(x * 0.5f));
    return fmaf(0.5f, t, 0.5f);
}

__device__ __forceinline__ void accum4(const float4& a, const float4& b,
                                       float& num, float& sp, float& st) {
    float s0 = fast_sigmoid(a.x);
    float s1 = fast_sigmoid(a.y);
    float s2 = fast_sigmoid(a.z);
    float s3 = fast_sigmoid(a.w);
    num += s0 * b.x + s1 * b.y + s2 * b.z + s3 * b.w;
    sp  += s0 + s1 + s2 + s3;
    st  += b.x + b.y + b.z + b.w;
}

__device__ __forceinline__ void cp_async16(void* smem_dst, const void* gmem_src) {
    unsigned int s = (unsigned int)__cvta_generic_to_shared(smem_dst);
    asm volatile("cp.async.cg.shared.global [%0], [%1], 16;" :: "r"(s), "l"(gmem_src));
}

__global__ __launch_bounds__(TPB)
void dice_fused_kernel(const float* __restrict__ predict,
                       const float* __restrict__ target,
                       float* __restrict__ out) {
    // Triple-buffered staging: [buf][tensor][idx] = 3*2*512 float4 = 48 KB.
    __shared__ float4 sbuf[KBUF][2][STAGE_F4];

    const int cta  = blockIdx.x;
    const int s    = cta / CTAS_PER_SLICE;
    const int part = cta % CTAS_PER_SLICE;
    const int tid  = threadIdx.x;

    const size_t base = (size_t)s * (HW / 4) + (size_t)part * CHUNK_F4;
    const float4* __restrict__ p = reinterpret_cast<const float4*>(predict) + base;
    const float4* __restrict__ t = reinterpret_cast<const float4*>(target)  + base;

    // Each thread copies and later consumes ITS OWN elements (idx = tid, tid+TPB)
    // within each stage -> no __syncthreads needed inside the pipeline.

    // Prologue: prefetch stages 0 and 1 into smem (two groups in flight).
    #pragma unroll
    for (int st_i = 0; st_i < KBUF - 1; ++st_i) {
        const int off = st_i * STAGE_F4;
        #pragma unroll
        for (int j = 0; j < F4_PER_THREAD; ++j) {
            const int idx = tid + j * TPB;
            cp_async16(&sbuf[st_i][0][idx], p + off + idx);
            cp_async16(&sbuf[st_i][1][idx], t + off + idx);
        }
        asm volatile("cp.async.commit_group;");
    }

    float num = 0.0f, sp = 0.0f, st = 0.0f;

    #pragma unroll
    for (int it = 0; it < NSTAGES; ++it) {
        const int cur = it % KBUF;
        if (it + KBUF - 1 < NSTAGES) {
            const int nxt = (it + KBUF - 1) % KBUF;
            const int off = (it + KBUF - 1) * STAGE_F4;
            #pragma unroll
            for (int j = 0; j < F4_PER_THREAD; ++j) {
                const int idx = tid + j * TPB;
                cp_async16(&sbuf[nxt][0][idx], p + off + idx);
                cp_async16(&sbuf[nxt][1][idx], t + off + idx);
            }
            asm volatile("cp.async.commit_group;");
            asm volatile("cp.async.wait_group %0;" :: "n"(KBUF - 1));
        } else {
            asm volatile("cp.async.wait_group 0;");
        }

        // Capture slice validity from data already staged in smem: the
        // part==0 CTA's stage 0, element 0 is target[slice*HW + 0].
        // (tid 0 owns idx 0 in this stage, so it wrote & can read it.)
        if (it == 0 && part == 0 && tid == 0) {
            g_valid[s] = (sbuf[0][1][0].x != -1.0f) ? 1.0f : 0.0f;
        }

        #pragma unroll
        for (int j = 0; j < F4_PER_THREAD; ++j) {
            const int idx = tid + j * TPB;
            accum4(sbuf[cur][0][idx], sbuf[cur][1][idx], num, sp, st);
        }
    }

    // Warp reduce the three accumulators.
    #pragma unroll
    for (int off = 16; off > 0; off >>= 1) {
        num += __shfl_down_sync(0xffffffffu, num, off);
        sp  += __shfl_down_sync(0xffffffffu, sp,  off);
        st  += __shfl_down_sync(0xffffffffu, st,  off);
    }

    __shared__ float s_num[TPB / 32];
    __shared__ float s_sp [TPB / 32];
    __shared__ float s_st [TPB / 32];
    __shared__ bool  s_last;

    const int lane = tid & 31;
    const int wid  = tid >> 5;
    if (lane == 0) { s_num[wid] = num; s_sp[wid] = sp; s_st[wid] = st; }
    __syncthreads();

    if (tid == 0) {
        float n = 0.0f, a = 0.0f, b = 0.0f;
        #pragma unroll
        for (int w = 0; w < TPB / 32; w++) { n += s_num[w]; a += s_sp[w]; b += s_st[w]; }
        atomicAdd(&g_num[s], n);
        atomicAdd(&g_sp [s], a);
        atomicAdd(&g_st [s], b);
        __threadfence();
        unsigned int d = atomicAdd(&g_done, 1u);
        s_last = (d == GRID - 1);
    }
    __syncthreads();

    // ---- Fused finalize: last CTA reduces all 512 slices ----
    if (s_last) {
        __threadfence();  // acquire: all producer atomics/stores visible

        __shared__ float p_sum[NPAIRS];
        __shared__ float p_cnt[NPAIRS];
        if (tid < NPAIRS) { p_sum[tid] = 0.0f; p_cnt[tid] = 0.0f; }
        __syncthreads();

        for (int i = tid; i < NSLICES; i += TPB) {
            float n = g_num[i];
            float a = g_sp [i];
            float b = g_st [i];
            float dice = 1.0f - 2.0f * n / (a + b + 1.0f);
            float v = g_valid[i];
            atomicAdd(&p_sum[i / SLICE_D], dice * v);
            atomicAdd(&p_cnt[i / SLICE_D], v);
            // Reset state for the next graph replay.
            g_num[i] = 0.0f; g_sp[i] = 0.0f; g_st[i] = 0.0f;
        }
        __syncthreads();

        if (tid == 0) {
            float acc = 0.0f;
            #pragma unroll
            for (int i = 0; i < NPAIRS; i++) acc += p_sum[i] / p_cnt[i];
            out[0] = acc * (1.0f / (float)NPAIRS);
            g_done = 0u;
        }
    }
}

extern "C" void kernel_launch(void* const* d_in, const int* in_sizes, int n_in,
                              void* d_out, int out_size) {
    const float* predict = (const float*)d_in[0];
    const float* target  = (const float*)d_in[1];
    float* out = (float*)d_out;

    dice_fused_kernel<<<GRID, TPB>>>(predict, target, out);
}

// round 15
// speedup vs baseline: 1.2136x; 1.2136x over previous
#include <cuda_runtime.h>
#include <cstdint>

// predict/target: [2, 4, 64, 256, 256] fp32 -> 512 slices of 65536 elems.
// Linear chunk decomposition: 4096 chunks of 2048 float4 (8 chunks per slice);
// chunk c covers float4 range [c*2048, (c+1)*2048), slice = c >> 3.
#define HW        65536
#define NSLICES   512
#define SLICE_D   64
#define NPAIRS    8
#define TPB       256
#define GRID      592                      // 4 CTAs/SM * 148 SMs, single wave
#define NCHUNKS   4096
#define BASE_CH   (NCHUNKS / GRID)         // 6
#define REM       (NCHUNKS - BASE_CH * GRID) // 544 CTAs get a 7th chunk
#define STAGE_F4  512                      // 8 KB per tensor per stage
#define KBUF      3                        // ring depth, 48 KB smem
#define F4T       (STAGE_F4 / TPB)         // 2

__device__ float        g_num[NSLICES];
__device__ float        g_sp [NSLICES];
__device__ float        g_st [NSLICES];
__device__ unsigned int g_done;

// sigmoid(x) = 0.5 * tanh(0.5 x) + 0.5  (tanh.approx.f32: 1 MUFU op)
__device__ __forceinline__ float fast_sigmoid(float x) {
    float t;
    asm("tanh.approx.f32 %0, %1;" : "=f"(t) : "f"(x * 0.5f));
    return fmaf(0.5f, t, 0.5f);
}

__device__ __forceinline__ void accum4(const float4& a, const float4& b,
                                       float& num, float& sp, float& st) {
    float s0 = fast_sigmoid(a.x);
    float s1 = fast_sigmoid(a.y);
    float s2 = fast_sigmoid(a.z);
    float s3 = fast_sigmoid(a.w);
    num += s0 * b.x + s1 * b.y + s2 * b.z + s3 * b.w;
    sp  += s0 + s1 + s2 + s3;
    st  += b.x + b.y + b.z + b.w;
}

__device__ __forceinline__ void cp_async16(void* smem_dst, const void* gmem_src) {
    unsigned int s = (unsigned int)__cvta_generic_to_shared(smem_dst);
    asm volatile("cp.async.cg.shared.global [%0], [%1], 16;" :: "r"(s), "l"(gmem_src));
}

__global__ __launch_bounds__(TPB)
void dice_fused_kernel(const float* __restrict__ predict,
                       const float* __restrict__ target,
                       float* __restrict__ out) {
    // Persistent ring: [buf][tensor][idx] = 3*2*512 float4 = 48 KB.
    __shared__ float4 sbuf[KBUF][2][STAGE_F4];
    __shared__ float s_num[TPB / 32];
    __shared__ float s_sp [TPB / 32];
    __shared__ float s_st [TPB / 32];
    __shared__ bool  s_last;

    const int cta  = blockIdx.x;
    const int tid  = threadIdx.x;
    const int lane = tid & 31;
    const int wid  = tid >> 5;

    // This CTA's chunks: c_k = cta + k*GRID, k = 0..nch-1 (6 or 7 chunks).
    const int nch = BASE_CH + (cta < REM ? 1 : 0);
    const int nst = nch * 4;                 // 4 stages per chunk

    const float4* __restrict__ p4 = reinterpret_cast<const float4*>(predict);
    const float4* __restrict__ t4 = reinterpret_cast<const float4*>(target);

    // Stage g (0..nst-1) of this CTA -> global float4 base:
    //   chunk = cta + (g>>2)*GRID,  base = (chunk*4 + (g&3)) * 512.

    // Prologue: issue stages 0..KBUF-2 (nst >= 24, no bound check needed).
    int gi = 0;
    #pragma unroll
    for (; gi < KBUF - 1; ++gi) {
        const int kb = gi % KBUF;
        const size_t b = ((size_t)(cta + (gi >> 2) * GRID) * 4 + (gi & 3)) * STAGE_F4;
        #pragma unroll
        for (int j = 0; j < F4T; ++j) {
            cp_async16(&sbuf[kb][0][tid + j * TPB], p4 + b + tid + j * TPB);
            cp_async16(&sbuf[kb][1][tid + j * TPB], t4 + b + tid + j * TPB);
        }
        asm volatile("cp.async.commit_group;");
    }

    float num = 0.0f, sp = 0.0f, st = 0.0f;

    #pragma unroll 1
    for (int gc = 0; gc < nst; ++gc) {
        if (gi < nst) {
            const int kb = gi % KBUF;
            const size_t b = ((size_t)(cta + (gi >> 2) * GRID) * 4 + (gi & 3)) * STAGE_F4;
            #pragma unroll
            for (int j = 0; j < F4T; ++j) {
                cp_async16(&sbuf[kb][0][tid + j * TPB], p4 + b + tid + j * TPB);
                cp_async16(&sbuf[kb][1][tid + j * TPB], t4 + b + tid + j * TPB);
            }
            asm volatile("cp.async.commit_group;");
            ++gi;
            asm volatile("cp.async.wait_group %0;" :: "n"(KBUF - 1));
        } else {
            asm volatile("cp.async.wait_group 0;");
        }

        const int kb = gc % KBUF;
        #pragma unroll
        for (int j = 0; j < F4T; ++j)
            accum4(sbuf[kb][0][tid + j * TPB], sbuf[kb][1][tid + j * TPB], num, sp, st);

        // Chunk boundary: flush accumulators to this chunk's slice.
        if ((gc & 3) == 3) {
            const int slice = (cta + (gc >> 2) * GRID) >> 3;
            #pragma unroll
            for (int off = 16; off > 0; off >>= 1) {
                num += __shfl_down_sync(0xffffffffu, num, off);
                sp  += __shfl_down_sync(0xffffffffu, sp,  off);
                st  += __shfl_down_sync(0xffffffffu, st,  off);
            }
            if (lane == 0) { s_num[wid] = num; s_sp[wid] = sp; s_st[wid] = st; }
            __syncthreads();
            if (tid == 0) {
                float n = 0.0f, a = 0.0f, b2 = 0.0f;
                #pragma unroll
                for (int w = 0; w < TPB / 32; ++w) {
                    n += s_num[w]; a += s_sp[w]; b2 += s_st[w];
                }
                atomicAdd(&g_num[slice], n);
                atomicAdd(&g_sp [slice], a);
                atomicAdd(&g_st [slice], b2);
            }
            num = 0.0f; sp = 0.0f; st = 0.0f;
            __syncthreads();   // protect s_* reuse next chunk
        }
    }

    if (tid == 0) {
        __threadfence();
        unsigned int d = atomicAdd(&g_done, 1u);
        s_last = (d == GRID - 1);
    }
    __syncthreads();

    // ---- Fused finalize: last CTA reduces all 512 slices ----
    if (s_last) {
        __threadfence();  // acquire: all producer atomics visible

        __shared__ float p_sum[NPAIRS];
        __shared__ float p_cnt[NPAIRS];
        if (tid < NPAIRS) { p_sum[tid] = 0.0f; p_cnt[tid] = 0.0f; }
        __syncthreads();

        for (int i = tid; i < NSLICES; i += TPB) {
            float n = g_num[i];
            float a = g_sp [i];
            float b = g_st [i];
            float dice = 1.0f - 2.0f * n / (a + b + 1.0f);
            float v = (target[(size_t)i * HW] != -1.0f) ? 1.0f : 0.0f;
            atomicAdd(&p_sum[i / SLICE_D], dice * v);
            atomicAdd(&p_cnt[i / SLICE_D], v);
            // Reset state for the next graph replay.
            g_num[i] = 0.0f; g_sp[i] = 0.0f; g_st[i] = 0.0f;
        }
        __syncthreads();

        if (tid == 0) {
            float acc = 0.0f;
            #pragma unroll
            for (int i = 0; i < NPAIRS; i++) acc += p_sum[i] / p_cnt[i];
            out[0] = acc * (1.0f / (float)NPAIRS);
            g_done = 0u;
        }
    }
}

extern "C" void kernel_launch(void* const* d_in, const int* in_sizes, int n_in,
                              void* d_out, int out_size) {
    const float* predict = (const float*)d_in[0];
    const float* target  = (const float*)d_in[1];
    float* out = (float*)d_out;

    dice_fused_kernel<<<GRID, TPB>>>(predict, target, out);
}